// round 9
// baseline (speedup 1.0000x reference)
#include <cuda_runtime.h>

// ---------------- problem constants ----------------
#define BB    4
#define NANCH 211200
#define CC    256
#define HH    200
#define WW    176
#define KK    4096

#define NBOX      (BB * NANCH)          // 844,800
#define BOX_ELEMS (NBOX * 7)            // 5,913,600

#define THREADS   512

#define GATHER_BLOCKS (BB * CC * 2)             // 2048: two y-halves per plane
#define DECODE_BLOCKS (NBOX / THREADS)          // 1650 (exact)
#define TOTAL_BLOCKS  (GATHER_BLOCKS + DECODE_BLOCKS)  // 3698

#define PLANE_FLOATS (HH * WW)          // 35,200
#define HALF_SPLIT   (100 * WW)         // 17,600 : first offset of half B
#define HALF_A_FLOATS (101 * WW)        // 17,776 (rows 0..100, incl boundary)
#define HALF_B_FLOATS (100 * WW)        // 17,600 (rows 100..199)
#define SMEM_BYTES   (HALF_A_FLOATS * 4)        // 71,104

// Precomputed per-(b,k): 4 clamped corner offsets + 4 validity-folded weights.
__device__ ushort4 g_off[BB * KK];
__device__ float4  g_wgt[BB * KK];

// ---------------- kernel 1: per-keypoint precompute ----------------
__global__ void precompute_kernel(const float* __restrict__ kp)
{
    int i = blockIdx.x * blockDim.x + threadIdx.x;
    if (i >= BB * KK) return;

    float x = kp[i * 3 + 0];
    float y = kp[i * 3 + 1];

    // --- coord transform (matches reference exactly) ---
    const float px = 0.05f * 8.0f;              // base_pixel_size * STRIDE
    float idx_x = x / px;
    float idx_y = (y + 40.0f) / px;
    idx_x = fminf(fmaxf(idx_x, 0.0f), (float)(WW - 1));
    idx_y = fminf(fmaxf(idx_y, 0.0f), (float)(HH - 1));
    float nx = 2.0f * (idx_x / (float)(WW - 2)) - 1.0f;
    float ny = 2.0f * (idx_y / (float)(HH - 2)) - 1.0f;
    // grid = flip(indices): width driven by ny, height by nx
    float ix = (ny + 1.0f) * 0.5f * (float)(WW - 1);
    float iy = (nx + 1.0f) * 0.5f * (float)(HH - 1);

    float x0f = floorf(ix);
    float y0f = floorf(iy);
    float wx = ix - x0f;
    float wy = iy - y0f;
    int x0 = (int)x0f, y0 = (int)y0f;
    int x1 = x0 + 1,   y1 = y0 + 1;

    float vx0 = (x0 >= 0 && x0 <= WW - 1) ? 1.0f : 0.0f;
    float vx1 = (x1 >= 0 && x1 <= WW - 1) ? 1.0f : 0.0f;
    float vy0 = (y0 >= 0 && y0 <= HH - 1) ? 1.0f : 0.0f;
    float vy1 = (y1 >= 0 && y1 <= HH - 1) ? 1.0f : 0.0f;

    int x0c = min(max(x0, 0), WW - 1);
    int x1c = min(max(x1, 0), WW - 1);
    int y0c = min(max(y0, 0), HH - 1);
    int y1c = min(max(y1, 0), HH - 1);

    g_off[i] = make_ushort4((unsigned short)(y0c * WW + x0c),
                            (unsigned short)(y0c * WW + x1c),
                            (unsigned short)(y1c * WW + x0c),
                            (unsigned short)(y1c * WW + x1c));
    g_wgt[i] = make_float4((1.0f - wx) * (1.0f - wy) * (vx0 * vy0),
                           wx          * (1.0f - wy) * (vx1 * vy0),
                           (1.0f - wx) * wy          * (vx0 * vy1),
                           wx          * wy          * (vx1 * vy1));
}

// ---------------- decode for one box ----------------
__device__ __forceinline__ void decode_one(const float* __restrict__ deltas,
                                           const float* __restrict__ anchors,
                                           float* __restrict__ out, int box)
{
    size_t base = (size_t)box * 7;
    float d0 = deltas[base + 0], d1 = deltas[base + 1], d2 = deltas[base + 2];
    float d3 = deltas[base + 3], d4 = deltas[base + 4], d5 = deltas[base + 5];
    float d6 = deltas[base + 6];
    float a0 = anchors[base + 0], a1 = anchors[base + 1], a2 = anchors[base + 2];
    float a3 = anchors[base + 3], a4 = anchors[base + 4], a5 = anchors[base + 5];
    float a6 = anchors[base + 6];

    float dnorm = sqrtf(a3 * a3 + a4 * a4);

    out[base + 0] = d0 * dnorm + a0;
    out[base + 1] = d1 * dnorm + a1;
    out[base + 2] = d2 * a5 + a2;
    out[base + 3] = expf(d3) * a3;
    out[base + 4] = expf(d4) * a4;
    out[base + 5] = expf(d5) * a5;
    out[base + 6] = d6 + a6;
}

// ---------------- gather: one y-half of one (b,c) plane ----------------
// half 0: rows [0, 101)  -> points with o.x <  HALF_SPLIT
// half 1: rows [100, 200)-> points with o.x >= HALF_SPLIT (rebased)
__device__ __forceinline__ void gather_half(int gidx,
                                            const float* __restrict__ fm,
                                            float* __restrict__ bev,
                                            float* __restrict__ smem)
{
    const int pl   = gidx >> 1;                 // plane index = b*CC + c
    const int half = gidx & 1;
    const int b    = pl >> 8;

    const int rowbase = half ? HALF_SPLIT : 0;
    const int nfloats = half ? HALF_B_FLOATS : HALF_A_FLOATS;

    const float4* __restrict__ src =
        (const float4*)(fm + (size_t)pl * PLANE_FLOATS + rowbase);
    float4* __restrict__ dst = (float4*)smem;

    // stage this half: <=4444 float4 / 512 threads
    {
        const int N4 = nfloats / 4;
        int i = threadIdx.x;
        #pragma unroll 8
        for (int t = 0; t < 8; t++, i += THREADS)   // 8*512 = 4096 <= 4400
            dst[i] = src[i];
        for (; i < N4; i += THREADS)
            dst[i] = src[i];
    }
    __syncthreads();

    // rebased view so precomputed offsets index directly
    const float* __restrict__ plane = smem - rowbase;

    float* __restrict__ orow = bev + (size_t)pl * KK;
    const int base = b * KK + threadIdx.x;

    #pragma unroll
    for (int t = 0; t < KK / THREADS; t++) {
        int idx = base + t * THREADS;
        ushort4 o = __ldg(&g_off[idx]);
        bool mine = half ? (o.x >= HALF_SPLIT) : (o.x < HALF_SPLIT);
        if (mine) {
            float4 w = __ldg(&g_wgt[idx]);
            float r = plane[o.x] * w.x
                    + plane[o.y] * w.y
                    + plane[o.z] * w.z
                    + plane[o.w] * w.w;
            orow[t * THREADS + threadIdx.x] = r;
        }
    }
}

// ---------------- fused kernel ----------------
// Interleave gather / decode roles so each wave mixes streaming with smem work.
__global__ void __launch_bounds__(THREADS)
fused_kernel(const float* __restrict__ deltas,
             const float* __restrict__ anchors,
             const float* __restrict__ fm,
             float* __restrict__ boxes,
             float* __restrict__ bev)
{
    extern __shared__ float smem[];
    const int blk = blockIdx.x;

    int gather_idx = -1, decode_idx = -1;
    if (blk < 2 * DECODE_BLOCKS) {              // first 3300 blocks: alternate
        if (blk & 1) decode_idx = blk >> 1;
        else         gather_idx = blk >> 1;
    } else {
        gather_idx = blk - DECODE_BLOCKS;       // 1650 .. 2047
    }

    if (gather_idx >= 0) {
        gather_half(gather_idx, fm, bev, smem);
    } else {
        int box = decode_idx * THREADS + threadIdx.x;
        decode_one(deltas, anchors, boxes, box);
    }
}

// ---------------- launch ----------------
extern "C" void kernel_launch(void* const* d_in, const int* in_sizes, int n_in,
                              void* d_out, int out_size)
{
    const float* deltas  = (const float*)d_in[0];
    const float* anchors = (const float*)d_in[1];
    const float* fm      = (const float*)d_in[2];
    const float* kp      = (const float*)d_in[3];

    float* boxes_out = (float*)d_out;
    float* bev_out   = (float*)d_out + BOX_ELEMS;

    // 1. per-keypoint offsets + weights (tiny)
    precompute_kernel<<<(BB * KK + 255) / 256, 256>>>(kp);

    // 2. fused gather + decode
    cudaFuncSetAttribute(fused_kernel,
                         cudaFuncAttributeMaxDynamicSharedMemorySize, SMEM_BYTES);
    fused_kernel<<<TOTAL_BLOCKS, THREADS, SMEM_BYTES>>>(
        deltas, anchors, fm, boxes_out, bev_out);

    (void)in_sizes; (void)n_in; (void)out_size;
}